// round 14
// baseline (speedup 1.0000x reference)
#include <cuda_runtime.h>
#include <cuda_fp16.h>
#include <mma.h>
#include <cstdint>

using namespace nvcuda;

#define NODES   68000
#define BATCH   4
#define NPROT   17000
#define CDIM    128
#define EMAX    2200000
#define PK      2125      // agg blocks per batch (2125*8 = 17000)
#define NLAYERS 3

#define SCAN_BLOCKS  64
#define SCAN_THREADS 256
#define SCAN_TOTAL   (SCAN_BLOCKS * SCAN_THREADS)
#define SCAN_CHUNK   ((NODES + SCAN_TOTAL - 1) / SCAN_TOTAL)

// ---------------- scratch (allocation-free: __device__ globals) ----------------
__device__ __align__(16) int    g_deg[NODES];
__device__ __align__(16) int    g_ptr[NODES + 1];
__device__ __align__(16) int    g_cursor[NODES];
__device__ __align__(16) int    g_csr[EMAX];
__device__ __align__(16) int    g_tpart[SCAN_TOTAL];
__device__ __align__(16) float  g_dinv[NODES];
__device__ __align__(16) __half g_xh[NODES * 256];     // fp16 copy of x
__device__ __align__(16) __half g_hs[NODES * CDIM];    // hs = dinv * (in @ W), fp16
__device__ __align__(16) __half g_in[NODES * CDIM];    // next-layer input (fp16)
__device__ __align__(16) float  g_ppart[NLAYERS * BATCH * CDIM * PK]; // pool partials
__device__ __align__(16) float  g_pooled[BATCH * CDIM];

// ---------------- fused: fp32->fp16 conversion of x + zero deg ----------------
__global__ void f2h_zero_kernel(const float* __restrict__ x, __half* __restrict__ xh,
                                int n4, int* __restrict__ deg, int n_deg) {
    int i = blockIdx.x * blockDim.x + threadIdx.x;
    int stride = gridDim.x * blockDim.x;
    for (int k = i; k < n_deg; k += stride) deg[k] = 0;
    for (int k = i; k < n4; k += stride) {
        float4 v = ((const float4*)x)[k];
        __half2 p0 = __floats2half2_rn(v.x, v.y);
        __half2 p1 = __floats2half2_rn(v.z, v.w);
        uint2 r;
        r.x = *(unsigned int*)&p0;
        r.y = *(unsigned int*)&p1;
        ((uint2*)xh)[k] = r;
    }
}

__global__ void deg_kernel(const int* __restrict__ dst, int* __restrict__ deg, int E) {
    int i = blockIdx.x * blockDim.x + threadIdx.x;
    if (i < E) atomicAdd(&deg[dst[i]], 1);
}

// ---------------- multi-block scan (phase 1 fused with dinv) -----------------
__global__ __launch_bounds__(SCAN_THREADS) void scan_p1_kernel(
    const int* __restrict__ deg, int* __restrict__ tpart, float* __restrict__ dinv)
{
    int t = blockIdx.x * blockDim.x + threadIdx.x;
    int lo = t * SCAN_CHUNK;
    int hi = lo + SCAN_CHUNK; if (hi > NODES) hi = NODES;
    int sum = 0;
    for (int i = lo; i < hi; i++) {
        int d = deg[i];
        sum += d;
        dinv[i] = rsqrtf((float)d + 1.0f);
    }
    tpart[t] = sum;
}

#define P2_T 1024
#define P2_PER (SCAN_TOTAL / P2_T)
__global__ __launch_bounds__(P2_T) void scan_p2_kernel(int* __restrict__ tpart)
{
    __shared__ int bs[P2_T];
    int t = threadIdx.x;
    int v[P2_PER];
    int local = 0;
#pragma unroll
    for (int i = 0; i < P2_PER; i++) {
        v[i] = tpart[t * P2_PER + i];
        local += v[i];
    }
    bs[t] = local;
    __syncthreads();
    for (int off = 1; off < P2_T; off <<= 1) {
        int x = 0;
        if (t >= off) x = bs[t - off];
        __syncthreads();
        if (t >= off) bs[t] += x;
        __syncthreads();
    }
    int run = (t == 0) ? 0 : bs[t - 1];
#pragma unroll
    for (int i = 0; i < P2_PER; i++) {
        tpart[t * P2_PER + i] = run;
        run += v[i];
    }
}

__global__ __launch_bounds__(SCAN_THREADS) void scan_p3_kernel(
    const int* __restrict__ deg, const int* __restrict__ tpart,
    int* __restrict__ ptr, int* __restrict__ cursor, int E)
{
    int t = blockIdx.x * blockDim.x + threadIdx.x;
    int lo = t * SCAN_CHUNK;
    int hi = lo + SCAN_CHUNK; if (hi > NODES) hi = NODES;
    int run = tpart[t];
    for (int i = lo; i < hi; i++) {
        ptr[i] = run;
        cursor[i] = run;
        run += deg[i];
    }
    if (t == 0) ptr[NODES] = E;
}

__global__ void build_csr_kernel(const int* __restrict__ src, const int* __restrict__ dst,
                                 int* __restrict__ cursor, int* __restrict__ csr, int E)
{
    int i = blockIdx.x * blockDim.x + threadIdx.x;
    if (i < E) {
        int d = dst[i];
        int pos = atomicAdd(&cursor[d], 1);
        csr[pos] = src[i];
    }
}

// ---------------- HGEMM (wmma, software-pipelined K loop) --------------------
// A: [M,K] fp16; W: [K,128] fp32 (converted during smem store phase).
// Next tile's global loads are issued into registers before the current tile's
// MMAs, hiding global latency behind tensor work.
#define GBM 128
#define GBK 32
#define LDA 40
#define LDB 136
#define LDC 132
#define SM_AS 0
#define SM_BS (GBM * LDA * 2)
#define SM_CS (SM_BS + GBK * LDB * 2)
#define SM_TOTAL (SM_CS + GBM * LDC * 4)

__global__ __launch_bounds__(256) void hgemm_kernel(
    const __half* __restrict__ A, const float* __restrict__ W,
    const float* __restrict__ dinv, __half* __restrict__ hs, int M, int K)
{
    extern __shared__ char smem[];
    __half* As = (__half*)(smem + SM_AS);
    __half* Bs = (__half*)(smem + SM_BS);
    float*  Cs = (float*)(smem + SM_CS);

    int tx = threadIdx.x;
    int row0 = blockIdx.x * GBM;
    int warp = tx >> 5;
    int wr = warp & 3;
    int wc = warp >> 2;

    // per-thread tile-load coordinates (fixed)
    // A: 2 float4 per thread (GBM*GBK halves / 8 / 256 = 2)
    int ar[2], ac[2];
#pragma unroll
    for (int j = 0; j < 2; j++) {
        int i = tx + j * 256;
        ar[j] = i >> 2;
        ac[j] = (i & 3) * 8;
    }
    // B: 4 float4 per thread (GBK*CDIM floats / 4 / 256 = 4)
    int br[4], bc[4];
#pragma unroll
    for (int j = 0; j < 4; j++) {
        int i = tx + j * 256;
        br[j] = i >> 5;
        bc[j] = (i & 31) * 4;
    }

    float4 aReg[2], bReg[4];

    auto load_tile = [&](int k0) {
#pragma unroll
        for (int j = 0; j < 2; j++) {
            int gr = row0 + ar[j];
            float4 v = make_float4(0.f, 0.f, 0.f, 0.f);
            if (gr < M) v = *(const float4*)&A[(size_t)gr * K + k0 + ac[j]];
            aReg[j] = v;
        }
#pragma unroll
        for (int j = 0; j < 4; j++)
            bReg[j] = *(const float4*)&W[(size_t)(k0 + br[j]) * CDIM + bc[j]];
    };

    auto store_tile = [&]() {
#pragma unroll
        for (int j = 0; j < 2; j++)
            *(float4*)&As[ar[j] * LDA + ac[j]] = aReg[j];
#pragma unroll
        for (int j = 0; j < 4; j++) {
            __half2 p0 = __floats2half2_rn(bReg[j].x, bReg[j].y);
            __half2 p1 = __floats2half2_rn(bReg[j].z, bReg[j].w);
            uint2 w;
            w.x = *(unsigned int*)&p0;
            w.y = *(unsigned int*)&p1;
            *(uint2*)&Bs[br[j] * LDB + bc[j]] = w;
        }
    };

    wmma::fragment<wmma::accumulator, 16, 16, 16, float> acc[2][4];
#pragma unroll
    for (int mi = 0; mi < 2; mi++)
#pragma unroll
        for (int ni = 0; ni < 4; ni++) wmma::fill_fragment(acc[mi][ni], 0.f);

    // prologue: load + stage tile 0
    load_tile(0);
    store_tile();
    __syncthreads();

    for (int k0 = 0; k0 < K; k0 += GBK) {
        bool more = (k0 + GBK) < K;
        if (more) load_tile(k0 + GBK);   // prefetch next tile into registers

#pragma unroll
        for (int ks = 0; ks < GBK; ks += 16) {
            wmma::fragment<wmma::matrix_a, 16, 16, 16, __half, wmma::row_major> af[2];
            wmma::fragment<wmma::matrix_b, 16, 16, 16, __half, wmma::row_major> bf[4];
#pragma unroll
            for (int mi = 0; mi < 2; mi++)
                wmma::load_matrix_sync(af[mi], &As[(wr * 32 + mi * 16) * LDA + ks], LDA);
#pragma unroll
            for (int ni = 0; ni < 4; ni++)
                wmma::load_matrix_sync(bf[ni], &Bs[ks * LDB + wc * 64 + ni * 16], LDB);
#pragma unroll
            for (int mi = 0; mi < 2; mi++)
#pragma unroll
                for (int ni = 0; ni < 4; ni++)
                    wmma::mma_sync(acc[mi][ni], af[mi], bf[ni], acc[mi][ni]);
        }
        __syncthreads();
        if (more) {
            store_tile();
            __syncthreads();
        }
    }

#pragma unroll
    for (int mi = 0; mi < 2; mi++)
#pragma unroll
        for (int ni = 0; ni < 4; ni++)
            wmma::store_matrix_sync(&Cs[(wr * 32 + mi * 16) * LDC + wc * 64 + ni * 16],
                                    acc[mi][ni], LDC, wmma::mem_row_major);
    __syncthreads();

    int col4 = (tx & 31) * 4;
    int rstart = tx >> 5;
    for (int r = rstart; r < GBM; r += 8) {
        int gr = row0 + r;
        if (gr < M) {
            float dv = dinv[gr];
            float c0 = Cs[r * LDC + col4 + 0] * dv;
            float c1 = Cs[r * LDC + col4 + 1] * dv;
            float c2 = Cs[r * LDC + col4 + 2] * dv;
            float c3 = Cs[r * LDC + col4 + 3] * dv;
            __half2 p0 = __floats2half2_rn(c0, c1);
            __half2 p1 = __floats2half2_rn(c2, c3);
            uint2 w;
            w.x = *(unsigned int*)&p0;
            w.y = *(unsigned int*)&p1;
            *(uint2*)&hs[(size_t)gr * CDIM + col4] = w;
        }
    }
}

// ---------------- aggregation: warp per dst node, 2 rows per LDG -------------
__global__ __launch_bounds__(256) void agg_kernel(
    const int* __restrict__ ptr, const int* __restrict__ csr,
    const float* __restrict__ dinv, const __half* __restrict__ hs,
    const float* __restrict__ bias, const int* __restrict__ mask,
    __half* __restrict__ nxt, float* __restrict__ ppart,
    int write_nxt, int layer)
{
    __shared__ float pbuf[8][CDIM];
    int tx = threadIdx.x;
    int lane = tx & 31;
    int warp = tx >> 5;
    int hl = lane >> 4;          // half-warp index (0: even edges, 1: odd)
    int li = lane & 15;
    int co = li * 8;             // 8 halves (16B) per lane
    int b = blockIdx.y;
    int node = b * NPROT + blockIdx.x * 8 + warp;

    int beg = __ldg(&ptr[node]);
    int end = __ldg(&ptr[node + 1]);

    float a0 = 0.f, a1 = 0.f, a2 = 0.f, a3 = 0.f;
    float a4 = 0.f, a5 = 0.f, a6 = 0.f, a7 = 0.f;

#define ACC_ROW(R)  do {                                              \
        float2 f;                                                     \
        f = __half22float2(*(__half2*)&(R).x); a0 += f.x; a1 += f.y;  \
        f = __half22float2(((__half2*)&(R).x)[1]); a2 += f.x; a3 += f.y; \
        f = __half22float2(*(__half2*)&(R).z); a4 += f.x; a5 += f.y;  \
        f = __half22float2(((__half2*)&(R).z)[1]); a6 += f.x; a7 += f.y; \
    } while (0)

    // self term: only half 0 accumulates (counted once after combine)
    if (hl == 0) {
        uint4 r = *(const uint4*)(hs + (size_t)node * CDIM + co);
        ACC_ROW(r);
    }

    int e = beg;
    for (; e + 8 <= end; e += 8) {
        int i0 = __ldg(&csr[e + 0 + hl]);
        int i1 = __ldg(&csr[e + 2 + hl]);
        int i2 = __ldg(&csr[e + 4 + hl]);
        int i3 = __ldg(&csr[e + 6 + hl]);
        uint4 r0 = *(const uint4*)(hs + (size_t)i0 * CDIM + co);
        uint4 r1 = *(const uint4*)(hs + (size_t)i1 * CDIM + co);
        uint4 r2 = *(const uint4*)(hs + (size_t)i2 * CDIM + co);
        uint4 r3 = *(const uint4*)(hs + (size_t)i3 * CDIM + co);
        ACC_ROW(r0);
        ACC_ROW(r1);
        ACC_ROW(r2);
        ACC_ROW(r3);
    }
    for (; e < end; e += 2) {
        if (e + hl < end) {
            int si = __ldg(&csr[e + hl]);
            uint4 r = *(const uint4*)(hs + (size_t)si * CDIM + co);
            ACC_ROW(r);
        }
    }
#undef ACC_ROW

    a0 += __shfl_down_sync(0xffffffffu, a0, 16);
    a1 += __shfl_down_sync(0xffffffffu, a1, 16);
    a2 += __shfl_down_sync(0xffffffffu, a2, 16);
    a3 += __shfl_down_sync(0xffffffffu, a3, 16);
    a4 += __shfl_down_sync(0xffffffffu, a4, 16);
    a5 += __shfl_down_sync(0xffffffffu, a5, 16);
    a6 += __shfl_down_sync(0xffffffffu, a6, 16);
    a7 += __shfl_down_sync(0xffffffffu, a7, 16);

    if (hl == 0) {
        float dv = dinv[node];
        float4 bA = *(const float4*)&bias[co];
        float4 bB = *(const float4*)&bias[co + 4];
        float r0 = fmaxf(a0 * dv + bA.x, 0.f);
        float r1 = fmaxf(a1 * dv + bA.y, 0.f);
        float r2 = fmaxf(a2 * dv + bA.z, 0.f);
        float r3 = fmaxf(a3 * dv + bA.w, 0.f);
        float r4 = fmaxf(a4 * dv + bB.x, 0.f);
        float r5 = fmaxf(a5 * dv + bB.y, 0.f);
        float r6 = fmaxf(a6 * dv + bB.z, 0.f);
        float r7 = fmaxf(a7 * dv + bB.w, 0.f);

        if (write_nxt) {
            __half2 p0 = __floats2half2_rn(r0, r1);
            __half2 p1 = __floats2half2_rn(r2, r3);
            __half2 p2 = __floats2half2_rn(r4, r5);
            __half2 p3 = __floats2half2_rn(r6, r7);
            uint4 w;
            w.x = *(unsigned int*)&p0;
            w.y = *(unsigned int*)&p1;
            w.z = *(unsigned int*)&p2;
            w.w = *(unsigned int*)&p3;
            *(uint4*)&nxt[(size_t)node * CDIM + co] = w;
        }

        float mf = __ldg(&mask[node]) ? 1.f : 0.f;
        float4 qa = make_float4(r0 * mf, r1 * mf, r2 * mf, r3 * mf);
        float4 qb = make_float4(r4 * mf, r5 * mf, r6 * mf, r7 * mf);
        *(float4*)&pbuf[warp][co] = qa;
        *(float4*)&pbuf[warp][co + 4] = qb;
    }
    __syncthreads();

    if (tx < CDIM) {
        float sum = 0.f;
#pragma unroll
        for (int w = 0; w < 8; w++) sum += pbuf[w][tx];
        ppart[(((size_t)layer * BATCH + b) * CDIM + tx) * PK + blockIdx.x] = sum;
    }
}

// ---------------- pool reduce ----------------
__global__ __launch_bounds__(256) void pool_reduce_kernel(
    const float* __restrict__ ppart, float* __restrict__ pooled)
{
    __shared__ float red[256];
    int bc = blockIdx.x;
    int tx = threadIdx.x;
    float sum = 0.f;
#pragma unroll
    for (int l = 0; l < NLAYERS; l++) {
        const float* row = ppart + (((size_t)l * BATCH) * CDIM + bc) * PK;
        for (int k = tx; k < PK; k += 256) sum += row[k];
    }
    red[tx] = sum;
    __syncthreads();
    for (int off = 128; off > 0; off >>= 1) {
        if (tx < off) red[tx] += red[tx + off];
        __syncthreads();
    }
    if (tx == 0) pooled[bc] = red[0];
}

// ---------------- tiny MLP ----------------
__global__ __launch_bounds__(256) void mlp_kernel(
    const float* __restrict__ pooled,
    const float* __restrict__ lw1, const float* __restrict__ lb1,
    const float* __restrict__ lw2, const float* __restrict__ lb2,
    const float* __restrict__ lw3, const float* __restrict__ lb3,
    const float* __restrict__ lw4, const float* __restrict__ lb4,
    float* __restrict__ out)
{
    __shared__ float sp[BATCH * 128];
    __shared__ float z1[BATCH * 256];
    __shared__ float z2[BATCH * 64];
    __shared__ float z3[BATCH * 16];
    int tx = threadIdx.x;

    for (int i = tx; i < BATCH * 128; i += 256) sp[i] = pooled[i];
    __syncthreads();

    for (int i = tx; i < BATCH * 256; i += 256) {
        int b = i >> 8, c = i & 255;
        float acc = lb1[c];
        for (int k = 0; k < 128; k++) acc += sp[b * 128 + k] * lw1[k * 256 + c];
        z1[i] = fmaxf(acc, 0.f);
    }
    __syncthreads();

    for (int i = tx; i < BATCH * 64; i += 256) {
        int b = i >> 6, c = i & 63;
        float acc = lb2[c];
        for (int k = 0; k < 256; k++) acc += z1[b * 256 + k] * lw2[k * 64 + c];
        z2[i] = fmaxf(acc, 0.f);
    }
    __syncthreads();

    if (tx < BATCH * 16) {
        int b = tx >> 4, c = tx & 15;
        float acc = lb3[c];
        for (int k = 0; k < 64; k++) acc += z2[b * 64 + k] * lw3[k * 16 + c];
        z3[tx] = fmaxf(acc, 0.f);
    }
    __syncthreads();

    if (tx < BATCH) {
        float acc = lb4[0];
        for (int k = 0; k < 16; k++) acc += z3[tx * 16 + k] * lw4[k];
        out[tx] = acc;
    }
}

// ---------------- launch ----------------
extern "C" void kernel_launch(void* const* d_in, const int* in_sizes, int n_in,
                              void* d_out, int out_size)
{
    const float* x    = (const float*)d_in[0];
    const int*   eidx = (const int*)d_in[1];
    const int*   mask = (const int*)d_in[2];
    const float* W1 = (const float*)d_in[3];  const float* b1 = (const float*)d_in[4];
    const float* W2 = (const float*)d_in[5];  const float* b2 = (const float*)d_in[6];
    const float* W3 = (const float*)d_in[7];  const float* b3 = (const float*)d_in[8];
    const float* lw1 = (const float*)d_in[9];  const float* lb1 = (const float*)d_in[10];
    const float* lw2 = (const float*)d_in[11]; const float* lb2 = (const float*)d_in[12];
    const float* lw3 = (const float*)d_in[13]; const float* lb3 = (const float*)d_in[14];
    const float* lw4 = (const float*)d_in[15]; const float* lb4 = (const float*)d_in[16];
    float* out = (float*)d_out;

    int M = NODES;
    int E = in_sizes[1] / 2;
    const int* src = eidx;
    const int* dst = eidx + E;

    void *p_deg, *p_ptr, *p_cur, *p_csr, *p_tp, *p_dinv, *p_xh, *p_hs, *p_in, *p_pp, *p_pool;
    cudaGetSymbolAddress(&p_deg, g_deg);
    cudaGetSymbolAddress(&p_ptr, g_ptr);
    cudaGetSymbolAddress(&p_cur, g_cursor);
    cudaGetSymbolAddress(&p_csr, g_csr);
    cudaGetSymbolAddress(&p_tp, g_tpart);
    cudaGetSymbolAddress(&p_dinv, g_dinv);
    cudaGetSymbolAddress(&p_xh, g_xh);
    cudaGetSymbolAddress(&p_hs, g_hs);
    cudaGetSymbolAddress(&p_in, g_in);
    cudaGetSymbolAddress(&p_pp, g_ppart);
    cudaGetSymbolAddress(&p_pool, g_pooled);
    int*    deg  = (int*)p_deg;
    int*    ptr  = (int*)p_ptr;
    int*    cur  = (int*)p_cur;
    int*    csr  = (int*)p_csr;
    int*    tp   = (int*)p_tp;
    float*  dinv = (float*)p_dinv;
    __half* xh   = (__half*)p_xh;
    __half* hs   = (__half*)p_hs;
    __half* in   = (__half*)p_in;
    float*  pp   = (float*)p_pp;
    float*  pool = (float*)p_pool;

    cudaFuncSetAttribute(hgemm_kernel, cudaFuncAttributeMaxDynamicSharedMemorySize, SM_TOTAL);

    dim3 agg_grid(PK, BATCH);
    int gemm_blocks = (M + GBM - 1) / GBM;

    // fused x conversion + deg zeroing
    f2h_zero_kernel<<<1024, 256>>>(x, xh, M * 256 / 4, deg, M);

    // degree count
    deg_kernel<<<(E + 255) / 256, 256>>>(dst, deg, E);

    // scan phase 1 fused with dinv
    scan_p1_kernel<<<SCAN_BLOCKS, SCAN_THREADS>>>(deg, tp, dinv);

    // layer-1 GEMM only needs xh + dinv — launch before the rest of the CSR chain
    hgemm_kernel<<<gemm_blocks, 256, SM_TOTAL>>>(xh, W1, dinv, hs, M, 256);

    scan_p2_kernel<<<1, P2_T>>>(tp);
    scan_p3_kernel<<<SCAN_BLOCKS, SCAN_THREADS>>>(deg, tp, ptr, cur, E);
    build_csr_kernel<<<(E + 255) / 256, 256>>>(src, dst, cur, csr, E);

    // layer 1 aggregation
    agg_kernel<<<agg_grid, 256>>>(ptr, csr, dinv, hs, b1, mask, in, pp, 1, 0);

    // layer 2
    hgemm_kernel<<<gemm_blocks, 256, SM_TOTAL>>>(in, W2, dinv, hs, M, 128);
    agg_kernel<<<agg_grid, 256>>>(ptr, csr, dinv, hs, b2, mask, in, pp, 1, 1);

    // layer 3 — no next-layer input needed
    hgemm_kernel<<<gemm_blocks, 256, SM_TOTAL>>>(in, W3, dinv, hs, M, 128);
    agg_kernel<<<agg_grid, 256>>>(ptr, csr, dinv, hs, b3, mask, in, pp, 0, 2);

    // pool reduce (no atomics)
    pool_reduce_kernel<<<BATCH * CDIM, 256>>>(pp, pool);

    // MLP head
    mlp_kernel<<<1, 256>>>(pool, lw1, lb1, lw2, lb2, lw3, lb3, lw4, lb4, out);
}

// round 15
// speedup vs baseline: 1.3920x; 1.3920x over previous
#include <cuda_runtime.h>
#include <cuda_fp16.h>
#include <mma.h>
#include <cstdint>

using namespace nvcuda;

#define NODES   68000
#define BATCH   4
#define NPROT   17000
#define CDIM    128
#define EMAX    2200000
#define PK      2125      // agg blocks per batch (2125*8 = 17000)
#define NLAYERS 3

#define SCAN_BLOCKS  64
#define SCAN_THREADS 256
#define SCAN_TOTAL   (SCAN_BLOCKS * SCAN_THREADS)
#define SCAN_CHUNK   ((NODES + SCAN_TOTAL - 1) / SCAN_TOTAL)

// ---------------- scratch (allocation-free: __device__ globals) ----------------
__device__ __align__(16) int    g_deg[NODES];
__device__ __align__(16) int    g_ptr[NODES + 1];
__device__ __align__(16) int    g_cursor[NODES];
__device__ __align__(16) int    g_csr[EMAX];
__device__ __align__(16) int    g_tpart[SCAN_TOTAL];
__device__ __align__(16) float  g_dinv[NODES];
__device__ __align__(16) __half g_xh[NODES * 256];     // fp16 copy of x
__device__ __align__(16) __half g_hs[NODES * CDIM];    // hs = dinv * (in @ W), fp16
__device__ __align__(16) __half g_in[NODES * CDIM];    // next-layer input (fp16)
__device__ __align__(16) float  g_ppart[NLAYERS * BATCH * CDIM * PK]; // pool partials
__device__ __align__(16) float  g_pooled[BATCH * CDIM];

// ---------------- fused: fp32->fp16 conversion of x + zero deg ----------------
__global__ void f2h_zero_kernel(const float* __restrict__ x, __half* __restrict__ xh,
                                int n4, int* __restrict__ deg, int n_deg) {
    int i = blockIdx.x * blockDim.x + threadIdx.x;
    int stride = gridDim.x * blockDim.x;
    for (int k = i; k < n_deg; k += stride) deg[k] = 0;
    for (int k = i; k < n4; k += stride) {
        float4 v = ((const float4*)x)[k];
        __half2 p0 = __floats2half2_rn(v.x, v.y);
        __half2 p1 = __floats2half2_rn(v.z, v.w);
        uint2 r;
        r.x = *(unsigned int*)&p0;
        r.y = *(unsigned int*)&p1;
        ((uint2*)xh)[k] = r;
    }
}

__global__ void deg_kernel(const int* __restrict__ dst, int* __restrict__ deg, int E) {
    int i = blockIdx.x * blockDim.x + threadIdx.x;
    if (i < E) atomicAdd(&deg[dst[i]], 1);
}

// ---------------- multi-block scan (phase 1 fused with dinv) -----------------
__global__ __launch_bounds__(SCAN_THREADS) void scan_p1_kernel(
    const int* __restrict__ deg, int* __restrict__ tpart, float* __restrict__ dinv)
{
    int t = blockIdx.x * blockDim.x + threadIdx.x;
    int lo = t * SCAN_CHUNK;
    int hi = lo + SCAN_CHUNK; if (hi > NODES) hi = NODES;
    int sum = 0;
    for (int i = lo; i < hi; i++) {
        int d = deg[i];
        sum += d;
        dinv[i] = rsqrtf((float)d + 1.0f);
    }
    tpart[t] = sum;
}

#define P2_T 1024
#define P2_PER (SCAN_TOTAL / P2_T)
__global__ __launch_bounds__(P2_T) void scan_p2_kernel(int* __restrict__ tpart)
{
    __shared__ int bs[P2_T];
    int t = threadIdx.x;
    int v[P2_PER];
    int local = 0;
#pragma unroll
    for (int i = 0; i < P2_PER; i++) {
        v[i] = tpart[t * P2_PER + i];
        local += v[i];
    }
    bs[t] = local;
    __syncthreads();
    for (int off = 1; off < P2_T; off <<= 1) {
        int x = 0;
        if (t >= off) x = bs[t - off];
        __syncthreads();
        if (t >= off) bs[t] += x;
        __syncthreads();
    }
    int run = (t == 0) ? 0 : bs[t - 1];
#pragma unroll
    for (int i = 0; i < P2_PER; i++) {
        tpart[t * P2_PER + i] = run;
        run += v[i];
    }
}

__global__ __launch_bounds__(SCAN_THREADS) void scan_p3_kernel(
    const int* __restrict__ deg, const int* __restrict__ tpart,
    int* __restrict__ ptr, int* __restrict__ cursor, int E)
{
    int t = blockIdx.x * blockDim.x + threadIdx.x;
    int lo = t * SCAN_CHUNK;
    int hi = lo + SCAN_CHUNK; if (hi > NODES) hi = NODES;
    int run = tpart[t];
    for (int i = lo; i < hi; i++) {
        ptr[i] = run;
        cursor[i] = run;
        run += deg[i];
    }
    if (t == 0) ptr[NODES] = E;
}

__global__ void build_csr_kernel(const int* __restrict__ src, const int* __restrict__ dst,
                                 int* __restrict__ cursor, int* __restrict__ csr, int E)
{
    int i = blockIdx.x * blockDim.x + threadIdx.x;
    if (i < E) {
        int d = dst[i];
        int pos = atomicAdd(&cursor[d], 1);
        csr[pos] = src[i];
    }
}

// ---------------- HGEMM (wmma): hs = fp16( rsqrt(deg+1) * (A @ W) ) ----------
// A: [M,K] fp16; W: [K,128] fp32 (converted during B-tile smem fill).
// Takes deg directly (computes rsqrt inline) so it depends only on deg_kernel,
// letting the whole scan/CSR chain run after/alongside it.
#define GBM 128
#define GBK 32
#define LDA 40
#define LDB 136
#define LDC 132
#define SM_AS 0
#define SM_BS (GBM * LDA * 2)
#define SM_CS (SM_BS + GBK * LDB * 2)
#define SM_TOTAL (SM_CS + GBM * LDC * 4)

__global__ __launch_bounds__(256) void hgemm_kernel(
    const __half* __restrict__ A, const float* __restrict__ W,
    const int* __restrict__ deg, __half* __restrict__ hs, int M, int K)
{
    extern __shared__ char smem[];
    __half* As = (__half*)(smem + SM_AS);
    __half* Bs = (__half*)(smem + SM_BS);
    float*  Cs = (float*)(smem + SM_CS);

    int tx = threadIdx.x;
    int row0 = blockIdx.x * GBM;
    int warp = tx >> 5;
    int wr = warp & 3;
    int wc = warp >> 2;

    wmma::fragment<wmma::accumulator, 16, 16, 16, float> acc[2][4];
#pragma unroll
    for (int mi = 0; mi < 2; mi++)
#pragma unroll
        for (int ni = 0; ni < 4; ni++) wmma::fill_fragment(acc[mi][ni], 0.f);

    for (int k0 = 0; k0 < K; k0 += GBK) {
        // ---- load A tile (fp16) ----
#pragma unroll
        for (int i = tx; i < GBM * GBK / 8; i += 256) {
            int r = i >> 2, c8 = (i & 3) * 8;
            int gr = row0 + r;
            float4 v = make_float4(0.f, 0.f, 0.f, 0.f);
            if (gr < M) v = *(const float4*)&A[(size_t)gr * K + k0 + c8];
            *(float4*)&As[r * LDA + c8] = v;
        }
        // ---- load B tile fp32 -> fp16 ----
#pragma unroll
        for (int i = tx; i < GBK * CDIM / 4; i += 256) {
            int r = i >> 5, c4 = (i & 31) * 4;
            float4 v = *(const float4*)&W[(size_t)(k0 + r) * CDIM + c4];
            __half2 p0 = __floats2half2_rn(v.x, v.y);
            __half2 p1 = __floats2half2_rn(v.z, v.w);
            uint2 w;
            w.x = *(unsigned int*)&p0;
            w.y = *(unsigned int*)&p1;
            *(uint2*)&Bs[r * LDB + c4] = w;
        }
        __syncthreads();
#pragma unroll
        for (int ks = 0; ks < GBK; ks += 16) {
            wmma::fragment<wmma::matrix_a, 16, 16, 16, __half, wmma::row_major> af[2];
            wmma::fragment<wmma::matrix_b, 16, 16, 16, __half, wmma::row_major> bf[4];
#pragma unroll
            for (int mi = 0; mi < 2; mi++)
                wmma::load_matrix_sync(af[mi], &As[(wr * 32 + mi * 16) * LDA + ks], LDA);
#pragma unroll
            for (int ni = 0; ni < 4; ni++)
                wmma::load_matrix_sync(bf[ni], &Bs[ks * LDB + wc * 64 + ni * 16], LDB);
#pragma unroll
            for (int mi = 0; mi < 2; mi++)
#pragma unroll
                for (int ni = 0; ni < 4; ni++)
                    wmma::mma_sync(acc[mi][ni], af[mi], bf[ni], acc[mi][ni]);
        }
        __syncthreads();
    }

#pragma unroll
    for (int mi = 0; mi < 2; mi++)
#pragma unroll
        for (int ni = 0; ni < 4; ni++)
            wmma::store_matrix_sync(&Cs[(wr * 32 + mi * 16) * LDC + wc * 64 + ni * 16],
                                    acc[mi][ni], LDC, wmma::mem_row_major);
    __syncthreads();

    int col4 = (tx & 31) * 4;
    int rstart = tx >> 5;
    for (int r = rstart; r < GBM; r += 8) {
        int gr = row0 + r;
        if (gr < M) {
            float dv = rsqrtf((float)deg[gr] + 1.0f);
            float c0 = Cs[r * LDC + col4 + 0] * dv;
            float c1 = Cs[r * LDC + col4 + 1] * dv;
            float c2 = Cs[r * LDC + col4 + 2] * dv;
            float c3 = Cs[r * LDC + col4 + 3] * dv;
            __half2 p0 = __floats2half2_rn(c0, c1);
            __half2 p1 = __floats2half2_rn(c2, c3);
            uint2 w;
            w.x = *(unsigned int*)&p0;
            w.y = *(unsigned int*)&p1;
            *(uint2*)&hs[(size_t)gr * CDIM + col4] = w;
        }
    }
}

// ---------------- aggregation: warp per dst node, 2 rows per LDG -------------
__global__ __launch_bounds__(256) void agg_kernel(
    const int* __restrict__ ptr, const int* __restrict__ csr,
    const float* __restrict__ dinv, const __half* __restrict__ hs,
    const float* __restrict__ bias, const int* __restrict__ mask,
    __half* __restrict__ nxt, float* __restrict__ ppart,
    int write_nxt, int layer)
{
    __shared__ float pbuf[8][CDIM];
    int tx = threadIdx.x;
    int lane = tx & 31;
    int warp = tx >> 5;
    int hl = lane >> 4;          // half-warp index (0: even edges, 1: odd)
    int li = lane & 15;
    int co = li * 8;             // 8 halves (16B) per lane
    int b = blockIdx.y;
    int node = b * NPROT + blockIdx.x * 8 + warp;

    int beg = __ldg(&ptr[node]);
    int end = __ldg(&ptr[node + 1]);

    float a0 = 0.f, a1 = 0.f, a2 = 0.f, a3 = 0.f;
    float a4 = 0.f, a5 = 0.f, a6 = 0.f, a7 = 0.f;

#define ACC_ROW(R)  do {                                              \
        float2 f;                                                     \
        f = __half22float2(*(__half2*)&(R).x); a0 += f.x; a1 += f.y;  \
        f = __half22float2(((__half2*)&(R).x)[1]); a2 += f.x; a3 += f.y; \
        f = __half22float2(*(__half2*)&(R).z); a4 += f.x; a5 += f.y;  \
        f = __half22float2(((__half2*)&(R).z)[1]); a6 += f.x; a7 += f.y; \
    } while (0)

    // self term: only half 0 accumulates (counted once after combine)
    if (hl == 0) {
        uint4 r = *(const uint4*)(hs + (size_t)node * CDIM + co);
        ACC_ROW(r);
    }

    int e = beg;
    for (; e + 8 <= end; e += 8) {
        int i0 = __ldg(&csr[e + 0 + hl]);
        int i1 = __ldg(&csr[e + 2 + hl]);
        int i2 = __ldg(&csr[e + 4 + hl]);
        int i3 = __ldg(&csr[e + 6 + hl]);
        uint4 r0 = *(const uint4*)(hs + (size_t)i0 * CDIM + co);
        uint4 r1 = *(const uint4*)(hs + (size_t)i1 * CDIM + co);
        uint4 r2 = *(const uint4*)(hs + (size_t)i2 * CDIM + co);
        uint4 r3 = *(const uint4*)(hs + (size_t)i3 * CDIM + co);
        ACC_ROW(r0);
        ACC_ROW(r1);
        ACC_ROW(r2);
        ACC_ROW(r3);
    }
    for (; e < end; e += 2) {
        if (e + hl < end) {
            int si = __ldg(&csr[e + hl]);
            uint4 r = *(const uint4*)(hs + (size_t)si * CDIM + co);
            ACC_ROW(r);
        }
    }
#undef ACC_ROW

    a0 += __shfl_down_sync(0xffffffffu, a0, 16);
    a1 += __shfl_down_sync(0xffffffffu, a1, 16);
    a2 += __shfl_down_sync(0xffffffffu, a2, 16);
    a3 += __shfl_down_sync(0xffffffffu, a3, 16);
    a4 += __shfl_down_sync(0xffffffffu, a4, 16);
    a5 += __shfl_down_sync(0xffffffffu, a5, 16);
    a6 += __shfl_down_sync(0xffffffffu, a6, 16);
    a7 += __shfl_down_sync(0xffffffffu, a7, 16);

    if (hl == 0) {
        float dv = dinv[node];
        float4 bA = *(const float4*)&bias[co];
        float4 bB = *(const float4*)&bias[co + 4];
        float r0 = fmaxf(a0 * dv + bA.x, 0.f);
        float r1 = fmaxf(a1 * dv + bA.y, 0.f);
        float r2 = fmaxf(a2 * dv + bA.z, 0.f);
        float r3 = fmaxf(a3 * dv + bA.w, 0.f);
        float r4 = fmaxf(a4 * dv + bB.x, 0.f);
        float r5 = fmaxf(a5 * dv + bB.y, 0.f);
        float r6 = fmaxf(a6 * dv + bB.z, 0.f);
        float r7 = fmaxf(a7 * dv + bB.w, 0.f);

        if (write_nxt) {
            __half2 p0 = __floats2half2_rn(r0, r1);
            __half2 p1 = __floats2half2_rn(r2, r3);
            __half2 p2 = __floats2half2_rn(r4, r5);
            __half2 p3 = __floats2half2_rn(r6, r7);
            uint4 w;
            w.x = *(unsigned int*)&p0;
            w.y = *(unsigned int*)&p1;
            w.z = *(unsigned int*)&p2;
            w.w = *(unsigned int*)&p3;
            *(uint4*)&nxt[(size_t)node * CDIM + co] = w;
        }

        float mf = __ldg(&mask[node]) ? 1.f : 0.f;
        float4 qa = make_float4(r0 * mf, r1 * mf, r2 * mf, r3 * mf);
        float4 qb = make_float4(r4 * mf, r5 * mf, r6 * mf, r7 * mf);
        *(float4*)&pbuf[warp][co] = qa;
        *(float4*)&pbuf[warp][co + 4] = qb;
    }
    __syncthreads();

    if (tx < CDIM) {
        float sum = 0.f;
#pragma unroll
        for (int w = 0; w < 8; w++) sum += pbuf[w][tx];
        ppart[(((size_t)layer * BATCH + b) * CDIM + tx) * PK + blockIdx.x] = sum;
    }
}

// ---------------- pool reduce ----------------
__global__ __launch_bounds__(256) void pool_reduce_kernel(
    const float* __restrict__ ppart, float* __restrict__ pooled)
{
    __shared__ float red[256];
    int bc = blockIdx.x;
    int tx = threadIdx.x;
    float sum = 0.f;
#pragma unroll
    for (int l = 0; l < NLAYERS; l++) {
        const float* row = ppart + (((size_t)l * BATCH) * CDIM + bc) * PK;
        for (int k = tx; k < PK; k += 256) sum += row[k];
    }
    red[tx] = sum;
    __syncthreads();
    for (int off = 128; off > 0; off >>= 1) {
        if (tx < off) red[tx] += red[tx + off];
        __syncthreads();
    }
    if (tx == 0) pooled[bc] = red[0];
}

// ---------------- tiny MLP ----------------
__global__ __launch_bounds__(256) void mlp_kernel(
    const float* __restrict__ pooled,
    const float* __restrict__ lw1, const float* __restrict__ lb1,
    const float* __restrict__ lw2, const float* __restrict__ lb2,
    const float* __restrict__ lw3, const float* __restrict__ lb3,
    const float* __restrict__ lw4, const float* __restrict__ lb4,
    float* __restrict__ out)
{
    __shared__ float sp[BATCH * 128];
    __shared__ float z1[BATCH * 256];
    __shared__ float z2[BATCH * 64];
    __shared__ float z3[BATCH * 16];
    int tx = threadIdx.x;

    for (int i = tx; i < BATCH * 128; i += 256) sp[i] = pooled[i];
    __syncthreads();

    for (int i = tx; i < BATCH * 256; i += 256) {
        int b = i >> 8, c = i & 255;
        float acc = lb1[c];
        for (int k = 0; k < 128; k++) acc += sp[b * 128 + k] * lw1[k * 256 + c];
        z1[i] = fmaxf(acc, 0.f);
    }
    __syncthreads();

    for (int i = tx; i < BATCH * 64; i += 256) {
        int b = i >> 6, c = i & 63;
        float acc = lb2[c];
        for (int k = 0; k < 256; k++) acc += z1[b * 256 + k] * lw2[k * 64 + c];
        z2[i] = fmaxf(acc, 0.f);
    }
    __syncthreads();

    if (tx < BATCH * 16) {
        int b = tx >> 4, c = tx & 15;
        float acc = lb3[c];
        for (int k = 0; k < 64; k++) acc += z2[b * 64 + k] * lw3[k * 16 + c];
        z3[tx] = fmaxf(acc, 0.f);
    }
    __syncthreads();

    if (tx < BATCH) {
        float acc = lb4[0];
        for (int k = 0; k < 16; k++) acc += z3[tx * 16 + k] * lw4[k];
        out[tx] = acc;
    }
}

// ---------------- launch ----------------
extern "C" void kernel_launch(void* const* d_in, const int* in_sizes, int n_in,
                              void* d_out, int out_size)
{
    const float* x    = (const float*)d_in[0];
    const int*   eidx = (const int*)d_in[1];
    const int*   mask = (const int*)d_in[2];
    const float* W1 = (const float*)d_in[3];  const float* b1 = (const float*)d_in[4];
    const float* W2 = (const float*)d_in[5];  const float* b2 = (const float*)d_in[6];
    const float* W3 = (const float*)d_in[7];  const float* b3 = (const float*)d_in[8];
    const float* lw1 = (const float*)d_in[9];  const float* lb1 = (const float*)d_in[10];
    const float* lw2 = (const float*)d_in[11]; const float* lb2 = (const float*)d_in[12];
    const float* lw3 = (const float*)d_in[13]; const float* lb3 = (const float*)d_in[14];
    const float* lw4 = (const float*)d_in[15]; const float* lb4 = (const float*)d_in[16];
    float* out = (float*)d_out;

    int M = NODES;
    int E = in_sizes[1] / 2;
    const int* src = eidx;
    const int* dst = eidx + E;

    void *p_deg, *p_ptr, *p_cur, *p_csr, *p_tp, *p_dinv, *p_xh, *p_hs, *p_in, *p_pp, *p_pool;
    cudaGetSymbolAddress(&p_deg, g_deg);
    cudaGetSymbolAddress(&p_ptr, g_ptr);
    cudaGetSymbolAddress(&p_cur, g_cursor);
    cudaGetSymbolAddress(&p_csr, g_csr);
    cudaGetSymbolAddress(&p_tp, g_tpart);
    cudaGetSymbolAddress(&p_dinv, g_dinv);
    cudaGetSymbolAddress(&p_xh, g_xh);
    cudaGetSymbolAddress(&p_hs, g_hs);
    cudaGetSymbolAddress(&p_in, g_in);
    cudaGetSymbolAddress(&p_pp, g_ppart);
    cudaGetSymbolAddress(&p_pool, g_pooled);
    int*    deg  = (int*)p_deg;
    int*    ptr  = (int*)p_ptr;
    int*    cur  = (int*)p_cur;
    int*    csr  = (int*)p_csr;
    int*    tp   = (int*)p_tp;
    float*  dinv = (float*)p_dinv;
    __half* xh   = (__half*)p_xh;
    __half* hs   = (__half*)p_hs;
    __half* in   = (__half*)p_in;
    float*  pp   = (float*)p_pp;
    float*  pool = (float*)p_pool;

    cudaFuncSetAttribute(hgemm_kernel, cudaFuncAttributeMaxDynamicSharedMemorySize, SM_TOTAL);

    dim3 agg_grid(PK, BATCH);
    int gemm_blocks = (M + GBM - 1) / GBM;

    // fused x conversion + deg zeroing
    f2h_zero_kernel<<<1024, 256>>>(x, xh, M * 256 / 4, deg, M);

    // degree count
    deg_kernel<<<(E + 255) / 256, 256>>>(dst, deg, E);

    // layer-1 GEMM needs only xh + deg — launch before the scan/CSR chain
    hgemm_kernel<<<gemm_blocks, 256, SM_TOTAL>>>(xh, W1, deg, hs, M, 256);

    // scan phase 1 fused with dinv (for agg)
    scan_p1_kernel<<<SCAN_BLOCKS, SCAN_THREADS>>>(deg, tp, dinv);
    scan_p2_kernel<<<1, P2_T>>>(tp);
    scan_p3_kernel<<<SCAN_BLOCKS, SCAN_THREADS>>>(deg, tp, ptr, cur, E);
    build_csr_kernel<<<(E + 255) / 256, 256>>>(src, dst, cur, csr, E);

    // layer 1 aggregation
    agg_kernel<<<agg_grid, 256>>>(ptr, csr, dinv, hs, b1, mask, in, pp, 1, 0);

    // layer 2
    hgemm_kernel<<<gemm_blocks, 256, SM_TOTAL>>>(in, W2, deg, hs, M, 128);
    agg_kernel<<<agg_grid, 256>>>(ptr, csr, dinv, hs, b2, mask, in, pp, 1, 1);

    // layer 3 — no next-layer input needed
    hgemm_kernel<<<gemm_blocks, 256, SM_TOTAL>>>(in, W3, deg, hs, M, 128);
    agg_kernel<<<agg_grid, 256>>>(ptr, csr, dinv, hs, b3, mask, in, pp, 0, 2);

    // pool reduce (no atomics)
    pool_reduce_kernel<<<BATCH * CDIM, 256>>>(pp, pool);

    // MLP head
    mlp_kernel<<<1, 256>>>(pool, lw1, lb1, lw2, lb2, lw3, lb3, lw4, lb4, out);
}

// round 16
// speedup vs baseline: 1.4112x; 1.0138x over previous
#include <cuda_runtime.h>
#include <cuda_fp16.h>
#include <mma.h>
#include <cstdint>

using namespace nvcuda;

#define NODES   68000
#define BATCH   4
#define NPROT   17000
#define CDIM    128
#define EMAX    2200000
#define PK      2125      // agg blocks per batch (2125*8 = 17000)
#define NLAYERS 3

#define SCAN_BLOCKS  64
#define SCAN_THREADS 256
#define SCAN_TOTAL   (SCAN_BLOCKS * SCAN_THREADS)
#define SCAN_CHUNK   ((NODES + SCAN_TOTAL - 1) / SCAN_TOTAL)

// ---------------- scratch (allocation-free: __device__ globals) ----------------
__device__ __align__(16) int    g_deg[NODES];
__device__ __align__(16) int    g_ptr[NODES + 1];
__device__ __align__(16) int    g_cursor[NODES];
__device__ __align__(16) int    g_csr[EMAX];
__device__ __align__(16) int    g_tpart[SCAN_TOTAL];
__device__ __align__(16) float  g_dinv[NODES];
__device__ __align__(16) __half g_xh[NODES * 256];     // fp16 copy of x
__device__ __align__(16) __half g_w1h[256 * CDIM];     // fp16 copies of weights
__device__ __align__(16) __half g_w2h[CDIM * CDIM];
__device__ __align__(16) __half g_w3h[CDIM * CDIM];
__device__ __align__(16) __half g_hs[NODES * CDIM];    // hs = dinv * (in @ W), fp16
__device__ __align__(16) __half g_in[NODES * CDIM];    // next-layer input (fp16)
__device__ __align__(16) float  g_ppart[NLAYERS * BATCH * CDIM * PK]; // pool partials
__device__ __align__(16) float  g_pooled[BATCH * CDIM];

// ---------------- fused: x + W1/W2/W3 fp32->fp16 conversion + zero deg -------
__device__ __forceinline__ void cvt_f4(const float4& v, uint2& r) {
    __half2 p0 = __floats2half2_rn(v.x, v.y);
    __half2 p1 = __floats2half2_rn(v.z, v.w);
    r.x = *(unsigned int*)&p0;
    r.y = *(unsigned int*)&p1;
}

__global__ void f2h_zero_kernel(const float* __restrict__ x, __half* __restrict__ xh, int n4,
                                const float* __restrict__ W1, __half* __restrict__ w1h, int n1,
                                const float* __restrict__ W2, __half* __restrict__ w2h, int n2,
                                const float* __restrict__ W3, __half* __restrict__ w3h, int n3,
                                int* __restrict__ deg, int n_deg) {
    int i = blockIdx.x * blockDim.x + threadIdx.x;
    int stride = gridDim.x * blockDim.x;
    for (int k = i; k < n_deg; k += stride) deg[k] = 0;
    for (int k = i; k < n1; k += stride) {
        uint2 r; cvt_f4(((const float4*)W1)[k], r); ((uint2*)w1h)[k] = r;
    }
    for (int k = i; k < n2; k += stride) {
        uint2 r; cvt_f4(((const float4*)W2)[k], r); ((uint2*)w2h)[k] = r;
    }
    for (int k = i; k < n3; k += stride) {
        uint2 r; cvt_f4(((const float4*)W3)[k], r); ((uint2*)w3h)[k] = r;
    }
    for (int k = i; k < n4; k += stride) {
        uint2 r; cvt_f4(((const float4*)x)[k], r); ((uint2*)xh)[k] = r;
    }
}

__global__ void deg_kernel(const int* __restrict__ dst, int* __restrict__ deg, int E) {
    int i = blockIdx.x * blockDim.x + threadIdx.x;
    if (i < E) atomicAdd(&deg[dst[i]], 1);
}

// ---------------- multi-block scan (phase 1 fused with dinv) -----------------
__global__ __launch_bounds__(SCAN_THREADS) void scan_p1_kernel(
    const int* __restrict__ deg, int* __restrict__ tpart, float* __restrict__ dinv)
{
    int t = blockIdx.x * blockDim.x + threadIdx.x;
    int lo = t * SCAN_CHUNK;
    int hi = lo + SCAN_CHUNK; if (hi > NODES) hi = NODES;
    int sum = 0;
    for (int i = lo; i < hi; i++) {
        int d = deg[i];
        sum += d;
        dinv[i] = rsqrtf((float)d + 1.0f);
    }
    tpart[t] = sum;
}

#define P2_T 1024
#define P2_PER (SCAN_TOTAL / P2_T)
__global__ __launch_bounds__(P2_T) void scan_p2_kernel(int* __restrict__ tpart)
{
    __shared__ int bs[P2_T];
    int t = threadIdx.x;
    int v[P2_PER];
    int local = 0;
#pragma unroll
    for (int i = 0; i < P2_PER; i++) {
        v[i] = tpart[t * P2_PER + i];
        local += v[i];
    }
    bs[t] = local;
    __syncthreads();
    for (int off = 1; off < P2_T; off <<= 1) {
        int x = 0;
        if (t >= off) x = bs[t - off];
        __syncthreads();
        if (t >= off) bs[t] += x;
        __syncthreads();
    }
    int run = (t == 0) ? 0 : bs[t - 1];
#pragma unroll
    for (int i = 0; i < P2_PER; i++) {
        tpart[t * P2_PER + i] = run;
        run += v[i];
    }
}

__global__ __launch_bounds__(SCAN_THREADS) void scan_p3_kernel(
    const int* __restrict__ deg, const int* __restrict__ tpart,
    int* __restrict__ ptr, int* __restrict__ cursor, int E)
{
    int t = blockIdx.x * blockDim.x + threadIdx.x;
    int lo = t * SCAN_CHUNK;
    int hi = lo + SCAN_CHUNK; if (hi > NODES) hi = NODES;
    int run = tpart[t];
    for (int i = lo; i < hi; i++) {
        ptr[i] = run;
        cursor[i] = run;
        run += deg[i];
    }
    if (t == 0) ptr[NODES] = E;
}

__global__ void build_csr_kernel(const int* __restrict__ src, const int* __restrict__ dst,
                                 int* __restrict__ cursor, int* __restrict__ csr, int E)
{
    int i = blockIdx.x * blockDim.x + threadIdx.x;
    if (i < E) {
        int d = dst[i];
        int pos = atomicAdd(&cursor[d], 1);
        csr[pos] = src[i];
    }
}

// ---------------- HGEMM (wmma): hs = fp16( dinv * (A @ W) ) ------------------
// A: [M,K] fp16; W: [K,128] fp16 (pre-converted in f2h_zero_kernel).
#define GBM 128
#define GBK 32
#define LDA 40
#define LDB 136
#define LDC 132
#define SM_AS 0
#define SM_BS (GBM * LDA * 2)
#define SM_CS (SM_BS + GBK * LDB * 2)
#define SM_TOTAL (SM_CS + GBM * LDC * 4)

__global__ __launch_bounds__(256) void hgemm_kernel(
    const __half* __restrict__ A, const __half* __restrict__ W,
    const float* __restrict__ dinv, __half* __restrict__ hs, int M, int K)
{
    extern __shared__ char smem[];
    __half* As = (__half*)(smem + SM_AS);
    __half* Bs = (__half*)(smem + SM_BS);
    float*  Cs = (float*)(smem + SM_CS);

    int tx = threadIdx.x;
    int row0 = blockIdx.x * GBM;
    int warp = tx >> 5;
    int wr = warp & 3;
    int wc = warp >> 2;

    wmma::fragment<wmma::accumulator, 16, 16, 16, float> acc[2][4];
#pragma unroll
    for (int mi = 0; mi < 2; mi++)
#pragma unroll
        for (int ni = 0; ni < 4; ni++) wmma::fill_fragment(acc[mi][ni], 0.f);

    for (int k0 = 0; k0 < K; k0 += GBK) {
        // ---- load A tile (fp16, 2 float4/thread) ----
#pragma unroll
        for (int i = tx; i < GBM * GBK / 8; i += 256) {
            int r = i >> 2, c8 = (i & 3) * 8;
            int gr = row0 + r;
            float4 v = make_float4(0.f, 0.f, 0.f, 0.f);
            if (gr < M) v = *(const float4*)&A[(size_t)gr * K + k0 + c8];
            *(float4*)&As[r * LDA + c8] = v;
        }
        // ---- load B tile (fp16, 2 float4/thread) ----
#pragma unroll
        for (int i = tx; i < GBK * CDIM / 8; i += 256) {
            int r = i >> 4, c8 = (i & 15) * 8;
            *(float4*)&Bs[r * LDB + c8] = *(const float4*)&W[(size_t)(k0 + r) * CDIM + c8];
        }
        __syncthreads();
#pragma unroll
        for (int ks = 0; ks < GBK; ks += 16) {
            wmma::fragment<wmma::matrix_a, 16, 16, 16, __half, wmma::row_major> af[2];
            wmma::fragment<wmma::matrix_b, 16, 16, 16, __half, wmma::row_major> bf[4];
#pragma unroll
            for (int mi = 0; mi < 2; mi++)
                wmma::load_matrix_sync(af[mi], &As[(wr * 32 + mi * 16) * LDA + ks], LDA);
#pragma unroll
            for (int ni = 0; ni < 4; ni++)
                wmma::load_matrix_sync(bf[ni], &Bs[ks * LDB + wc * 64 + ni * 16], LDB);
#pragma unroll
            for (int mi = 0; mi < 2; mi++)
#pragma unroll
                for (int ni = 0; ni < 4; ni++)
                    wmma::mma_sync(acc[mi][ni], af[mi], bf[ni], acc[mi][ni]);
        }
        __syncthreads();
    }

#pragma unroll
    for (int mi = 0; mi < 2; mi++)
#pragma unroll
        for (int ni = 0; ni < 4; ni++)
            wmma::store_matrix_sync(&Cs[(wr * 32 + mi * 16) * LDC + wc * 64 + ni * 16],
                                    acc[mi][ni], LDC, wmma::mem_row_major);
    __syncthreads();

    int col4 = (tx & 31) * 4;
    int rstart = tx >> 5;
    for (int r = rstart; r < GBM; r += 8) {
        int gr = row0 + r;
        if (gr < M) {
            float dv = dinv[gr];
            float c0 = Cs[r * LDC + col4 + 0] * dv;
            float c1 = Cs[r * LDC + col4 + 1] * dv;
            float c2 = Cs[r * LDC + col4 + 2] * dv;
            float c3 = Cs[r * LDC + col4 + 3] * dv;
            __half2 p0 = __floats2half2_rn(c0, c1);
            __half2 p1 = __floats2half2_rn(c2, c3);
            uint2 w;
            w.x = *(unsigned int*)&p0;
            w.y = *(unsigned int*)&p1;
            *(uint2*)&hs[(size_t)gr * CDIM + col4] = w;
        }
    }
}

// ---------------- aggregation: warp per dst node, 2 rows per LDG -------------
__global__ __launch_bounds__(256) void agg_kernel(
    const int* __restrict__ ptr, const int* __restrict__ csr,
    const float* __restrict__ dinv, const __half* __restrict__ hs,
    const float* __restrict__ bias, const int* __restrict__ mask,
    __half* __restrict__ nxt, float* __restrict__ ppart,
    int write_nxt, int layer)
{
    __shared__ float pbuf[8][CDIM];
    int tx = threadIdx.x;
    int lane = tx & 31;
    int warp = tx >> 5;
    int hl = lane >> 4;          // half-warp index (0: even edges, 1: odd)
    int li = lane & 15;
    int co = li * 8;             // 8 halves (16B) per lane
    int b = blockIdx.y;
    int node = b * NPROT + blockIdx.x * 8 + warp;

    int beg = __ldg(&ptr[node]);
    int end = __ldg(&ptr[node + 1]);

    float a0 = 0.f, a1 = 0.f, a2 = 0.f, a3 = 0.f;
    float a4 = 0.f, a5 = 0.f, a6 = 0.f, a7 = 0.f;

#define ACC_ROW(R)  do {                                              \
        float2 f;                                                     \
        f = __half22float2(*(__half2*)&(R).x); a0 += f.x; a1 += f.y;  \
        f = __half22float2(((__half2*)&(R).x)[1]); a2 += f.x; a3 += f.y; \
        f = __half22float2(*(__half2*)&(R).z); a4 += f.x; a5 += f.y;  \
        f = __half22float2(((__half2*)&(R).z)[1]); a6 += f.x; a7 += f.y; \
    } while (0)

    // self term: only half 0 accumulates (counted once after combine)
    if (hl == 0) {
        uint4 r = *(const uint4*)(hs + (size_t)node * CDIM + co);
        ACC_ROW(r);
    }

    int e = beg;
    for (; e + 8 <= end; e += 8) {
        int i0 = __ldg(&csr[e + 0 + hl]);
        int i1 = __ldg(&csr[e + 2 + hl]);
        int i2 = __ldg(&csr[e + 4 + hl]);
        int i3 = __ldg(&csr[e + 6 + hl]);
        uint4 r0 = *(const uint4*)(hs + (size_t)i0 * CDIM + co);
        uint4 r1 = *(const uint4*)(hs + (size_t)i1 * CDIM + co);
        uint4 r2 = *(const uint4*)(hs + (size_t)i2 * CDIM + co);
        uint4 r3 = *(const uint4*)(hs + (size_t)i3 * CDIM + co);
        ACC_ROW(r0);
        ACC_ROW(r1);
        ACC_ROW(r2);
        ACC_ROW(r3);
    }
    for (; e < end; e += 2) {
        if (e + hl < end) {
            int si = __ldg(&csr[e + hl]);
            uint4 r = *(const uint4*)(hs + (size_t)si * CDIM + co);
            ACC_ROW(r);
        }
    }
#undef ACC_ROW

    a0 += __shfl_down_sync(0xffffffffu, a0, 16);
    a1 += __shfl_down_sync(0xffffffffu, a1, 16);
    a2 += __shfl_down_sync(0xffffffffu, a2, 16);
    a3 += __shfl_down_sync(0xffffffffu, a3, 16);
    a4 += __shfl_down_sync(0xffffffffu, a4, 16);
    a5 += __shfl_down_sync(0xffffffffu, a5, 16);
    a6 += __shfl_down_sync(0xffffffffu, a6, 16);
    a7 += __shfl_down_sync(0xffffffffu, a7, 16);

    if (hl == 0) {
        float dv = dinv[node];
        float4 bA = *(const float4*)&bias[co];
        float4 bB = *(const float4*)&bias[co + 4];
        float r0 = fmaxf(a0 * dv + bA.x, 0.f);
        float r1 = fmaxf(a1 * dv + bA.y, 0.f);
        float r2 = fmaxf(a2 * dv + bA.z, 0.f);
        float r3 = fmaxf(a3 * dv + bA.w, 0.f);
        float r4 = fmaxf(a4 * dv + bB.x, 0.f);
        float r5 = fmaxf(a5 * dv + bB.y, 0.f);
        float r6 = fmaxf(a6 * dv + bB.z, 0.f);
        float r7 = fmaxf(a7 * dv + bB.w, 0.f);

        if (write_nxt) {
            __half2 p0 = __floats2half2_rn(r0, r1);
            __half2 p1 = __floats2half2_rn(r2, r3);
            __half2 p2 = __floats2half2_rn(r4, r5);
            __half2 p3 = __floats2half2_rn(r6, r7);
            uint4 w;
            w.x = *(unsigned int*)&p0;
            w.y = *(unsigned int*)&p1;
            w.z = *(unsigned int*)&p2;
            w.w = *(unsigned int*)&p3;
            *(uint4*)&nxt[(size_t)node * CDIM + co] = w;
        }

        float mf = __ldg(&mask[node]) ? 1.f : 0.f;
        float4 qa = make_float4(r0 * mf, r1 * mf, r2 * mf, r3 * mf);
        float4 qb = make_float4(r4 * mf, r5 * mf, r6 * mf, r7 * mf);
        *(float4*)&pbuf[warp][co] = qa;
        *(float4*)&pbuf[warp][co + 4] = qb;
    }
    __syncthreads();

    if (tx < CDIM) {
        float sum = 0.f;
#pragma unroll
        for (int w = 0; w < 8; w++) sum += pbuf[w][tx];
        ppart[(((size_t)layer * BATCH + b) * CDIM + tx) * PK + blockIdx.x] = sum;
    }
}

// ---------------- pool reduce ----------------
__global__ __launch_bounds__(256) void pool_reduce_kernel(
    const float* __restrict__ ppart, float* __restrict__ pooled)
{
    __shared__ float red[256];
    int bc = blockIdx.x;
    int tx = threadIdx.x;
    float sum = 0.f;
#pragma unroll
    for (int l = 0; l < NLAYERS; l++) {
        const float* row = ppart + (((size_t)l * BATCH) * CDIM + bc) * PK;
        for (int k = tx; k < PK; k += 256) sum += row[k];
    }
    red[tx] = sum;
    __syncthreads();
    for (int off = 128; off > 0; off >>= 1) {
        if (tx < off) red[tx] += red[tx + off];
        __syncthreads();
    }
    if (tx == 0) pooled[bc] = red[0];
}

// ---------------- tiny MLP ----------------
__global__ __launch_bounds__(256) void mlp_kernel(
    const float* __restrict__ pooled,
    const float* __restrict__ lw1, const float* __restrict__ lb1,
    const float* __restrict__ lw2, const float* __restrict__ lb2,
    const float* __restrict__ lw3, const float* __restrict__ lb3,
    const float* __restrict__ lw4, const float* __restrict__ lb4,
    float* __restrict__ out)
{
    __shared__ float sp[BATCH * 128];
    __shared__ float z1[BATCH * 256];
    __shared__ float z2[BATCH * 64];
    __shared__ float z3[BATCH * 16];
    int tx = threadIdx.x;

    for (int i = tx; i < BATCH * 128; i += 256) sp[i] = pooled[i];
    __syncthreads();

    for (int i = tx; i < BATCH * 256; i += 256) {
        int b = i >> 8, c = i & 255;
        float acc = lb1[c];
        for (int k = 0; k < 128; k++) acc += sp[b * 128 + k] * lw1[k * 256 + c];
        z1[i] = fmaxf(acc, 0.f);
    }
    __syncthreads();

    for (int i = tx; i < BATCH * 64; i += 256) {
        int b = i >> 6, c = i & 63;
        float acc = lb2[c];
        for (int k = 0; k < 256; k++) acc += z1[b * 256 + k] * lw2[k * 64 + c];
        z2[i] = fmaxf(acc, 0.f);
    }
    __syncthreads();

    if (tx < BATCH * 16) {
        int b = tx >> 4, c = tx & 15;
        float acc = lb3[c];
        for (int k = 0; k < 64; k++) acc += z2[b * 64 + k] * lw3[k * 16 + c];
        z3[tx] = fmaxf(acc, 0.f);
    }
    __syncthreads();

    if (tx < BATCH) {
        float acc = lb4[0];
        for (int k = 0; k < 16; k++) acc += z3[tx * 16 + k] * lw4[k];
        out[tx] = acc;
    }
}

// ---------------- launch ----------------
extern "C" void kernel_launch(void* const* d_in, const int* in_sizes, int n_in,
                              void* d_out, int out_size)
{
    const float* x    = (const float*)d_in[0];
    const int*   eidx = (const int*)d_in[1];
    const int*   mask = (const int*)d_in[2];
    const float* W1 = (const float*)d_in[3];  const float* b1 = (const float*)d_in[4];
    const float* W2 = (const float*)d_in[5];  const float* b2 = (const float*)d_in[6];
    const float* W3 = (const float*)d_in[7];  const float* b3 = (const float*)d_in[8];
    const float* lw1 = (const float*)d_in[9];  const float* lb1 = (const float*)d_in[10];
    const float* lw2 = (const float*)d_in[11]; const float* lb2 = (const float*)d_in[12];
    const float* lw3 = (const float*)d_in[13]; const float* lb3 = (const float*)d_in[14];
    const float* lw4 = (const float*)d_in[15]; const float* lb4 = (const float*)d_in[16];
    float* out = (float*)d_out;

    int M = NODES;
    int E = in_sizes[1] / 2;
    const int* src = eidx;
    const int* dst = eidx + E;

    void *p_deg, *p_ptr, *p_cur, *p_csr, *p_tp, *p_dinv, *p_xh, *p_w1h, *p_w2h, *p_w3h,
         *p_hs, *p_in, *p_pp, *p_pool;
    cudaGetSymbolAddress(&p_deg, g_deg);
    cudaGetSymbolAddress(&p_ptr, g_ptr);
    cudaGetSymbolAddress(&p_cur, g_cursor);
    cudaGetSymbolAddress(&p_csr, g_csr);
    cudaGetSymbolAddress(&p_tp, g_tpart);
    cudaGetSymbolAddress(&p_dinv, g_dinv);
    cudaGetSymbolAddress(&p_xh, g_xh);
    cudaGetSymbolAddress(&p_w1h, g_w1h);
    cudaGetSymbolAddress(&p_w2h, g_w2h);
    cudaGetSymbolAddress(&p_w3h, g_w3h);
    cudaGetSymbolAddress(&p_hs, g_hs);
    cudaGetSymbolAddress(&p_in, g_in);
    cudaGetSymbolAddress(&p_pp, g_ppart);
    cudaGetSymbolAddress(&p_pool, g_pooled);
    int*    deg  = (int*)p_deg;
    int*    ptr  = (int*)p_ptr;
    int*    cur  = (int*)p_cur;
    int*    csr  = (int*)p_csr;
    int*    tp   = (int*)p_tp;
    float*  dinv = (float*)p_dinv;
    __half* xh   = (__half*)p_xh;
    __half* w1h  = (__half*)p_w1h;
    __half* w2h  = (__half*)p_w2h;
    __half* w3h  = (__half*)p_w3h;
    __half* hs   = (__half*)p_hs;
    __half* in   = (__half*)p_in;
    float*  pp   = (float*)p_pp;
    float*  pool = (float*)p_pool;

    cudaFuncSetAttribute(hgemm_kernel, cudaFuncAttributeMaxDynamicSharedMemorySize, SM_TOTAL);

    dim3 agg_grid(PK, BATCH);
    int gemm_blocks = (M + GBM - 1) / GBM;

    // fused x + W conversions + deg zeroing (one streaming kernel)
    f2h_zero_kernel<<<1024, 256>>>(x, xh, M * 256 / 4,
                                   W1, w1h, 256 * CDIM / 4,
                                   W2, w2h, CDIM * CDIM / 4,
                                   W3, w3h, CDIM * CDIM / 4,
                                   deg, M);

    // degree count
    deg_kernel<<<(E + 255) / 256, 256>>>(dst, deg, E);

    // scan phase 1 fused with dinv
    scan_p1_kernel<<<SCAN_BLOCKS, SCAN_THREADS>>>(deg, tp, dinv);

    // layer-1 GEMM (needs xh + w1h + dinv) — launch before the rest of the CSR chain
    hgemm_kernel<<<gemm_blocks, 256, SM_TOTAL>>>(xh, w1h, dinv, hs, M, 256);

    scan_p2_kernel<<<1, P2_T>>>(tp);
    scan_p3_kernel<<<SCAN_BLOCKS, SCAN_THREADS>>>(deg, tp, ptr, cur, E);
    build_csr_kernel<<<(E + 255) / 256, 256>>>(src, dst, cur, csr, E);

    // layer 1 aggregation
    agg_kernel<<<agg_grid, 256>>>(ptr, csr, dinv, hs, b1, mask, in, pp, 1, 0);

    // layer 2
    hgemm_kernel<<<gemm_blocks, 256, SM_TOTAL>>>(in, w2h, dinv, hs, M, 128);
    agg_kernel<<<agg_grid, 256>>>(ptr, csr, dinv, hs, b2, mask, in, pp, 1, 1);

    // layer 3 — no next-layer input needed
    hgemm_kernel<<<gemm_blocks, 256, SM_TOTAL>>>(in, w3h, dinv, hs, M, 128);
    agg_kernel<<<agg_grid, 256>>>(ptr, csr, dinv, hs, b3, mask, in, pp, 0, 2);

    // pool reduce (no atomics)
    pool_reduce_kernel<<<BATCH * CDIM, 256>>>(pp, pool);

    // MLP head
    mlp_kernel<<<1, 256>>>(pool, lw1, lb1, lw2, lb2, lw3, lb3, lw4, lb4, out);
}